// round 17
// baseline (speedup 1.0000x reference)
#include <cuda_runtime.h>
#include <cuda_fp16.h>
#include <cstdint>

#define NN 89250
#define NE 899756
#define F0 500
#define HID 256
#define NC  7
#define SCAN_T 256
#define NBLK ((NN + SCAN_T - 1) / SCAN_T)   // 349
#define KP1 512                              // layer-1 K padded
#define KP2 256

// ---------------- scratch (device globals) ---------------------------------
__device__ __align__(256) uint32_t g_h1[(size_t)NN * 128];
__device__ __align__(256) uint32_t g_h2[(size_t)NN * 128];
__device__ __align__(256) uint32_t g_p3[(size_t)NN * 128];  // layer-3 P (pre-agg)
__device__ __align__(256) uint32_t g_q [(size_t)NN * 128];
__device__ __align__(256) __half g_w1t[2 * 256 * KP1];
__device__ __align__(256) __half g_w2t[2 * 256 * KP2];
__device__ __align__(256) __half g_w3t[2 * 256 * KP2];
__device__ int   g_cnt[NN];
__device__ int   g_row_start[NN];
__device__ int   g_row_fill[NN];
__device__ int   g_bsum[NBLK];
__device__ __align__(256) int2 g_csr[NE];   // {src, weight-bits} packed

#define W1TN (2 * 256 * KP1)   // 262144
#define W2TN (2 * 256 * KP2)   // 131072

// ---------------- CSR build kernels -----------------------------------------
__global__ void zero_cnt() {
    int i = blockIdx.x * blockDim.x + threadIdx.x;
    if (i < NN) g_cnt[i] = 0;
}
__global__ void count_kernel(const int* __restrict__ dst) {
    int e = blockIdx.x * blockDim.x + threadIdx.x;
    if (e < NE) atomicAdd(&g_cnt[dst[e]], 1);
}
__global__ void scanA() {
    __shared__ int s[SCAN_T];
    int t = threadIdx.x;
    int i = blockIdx.x * SCAN_T + t;
    s[t] = (i < NN) ? g_cnt[i] : 0;
    __syncthreads();
#pragma unroll
    for (int off = SCAN_T / 2; off > 0; off >>= 1) {
        if (t < off) s[t] += s[t + off];
        __syncthreads();
    }
    if (t == 0) g_bsum[blockIdx.x] = s[0];
}
__global__ void scanB() {
    __shared__ int s[512];
    int t = threadIdx.x;
    int v = (t < NBLK) ? g_bsum[t] : 0;
    s[t] = v;
    __syncthreads();
#pragma unroll
    for (int off = 1; off < 512; off <<= 1) {
        int x = (t >= off) ? s[t - off] : 0;
        __syncthreads();
        s[t] += x;
        __syncthreads();
    }
    if (t < NBLK) g_bsum[t] = s[t] - v;   // exclusive
}
__global__ void scanC() {
    __shared__ int s[SCAN_T];
    int t = threadIdx.x;
    int i = blockIdx.x * SCAN_T + t;
    int v = (i < NN) ? g_cnt[i] : 0;
    s[t] = v;
    __syncthreads();
#pragma unroll
    for (int off = 1; off < SCAN_T; off <<= 1) {
        int x = (t >= off) ? s[t - off] : 0;
        __syncthreads();
        s[t] += x;
        __syncthreads();
    }
    if (i < NN) {
        int excl = s[t] - v + g_bsum[blockIdx.x];
        g_row_start[i] = excl;
        g_row_fill[i]  = excl;
    }
}
__global__ void place_kernel(const int* __restrict__ src, const int* __restrict__ dst,
                             const float* __restrict__ ew) {
    int e = blockIdx.x * blockDim.x + threadIdx.x;
    if (e >= NE) return;
    int d = dst[e];
    int slot = atomicAdd(&g_row_fill[d], 1);
    float w = ew[e] / fmaxf((float)g_cnt[d], 1.0f);
    g_csr[slot] = make_int2(src[e], __float_as_int(w));
}

// ---------------- fp16 helpers -----------------------------------------------
__device__ __forceinline__ void mma_fp16(float c[4], const uint32_t a[4],
                                         uint32_t b0, uint32_t b1) {
    asm volatile(
        "mma.sync.aligned.m16n8k16.row.col.f32.f16.f16.f32 "
        "{%0,%1,%2,%3}, {%4,%5,%6,%7}, {%8,%9}, {%0,%1,%2,%3};"
        : "+f"(c[0]), "+f"(c[1]), "+f"(c[2]), "+f"(c[3])
        : "r"(a[0]), "r"(a[1]), "r"(a[2]), "r"(a[3]), "r"(b0), "r"(b1));
}
__device__ __forceinline__ void ldsm4(uint32_t r[4], uint32_t addr) {
    asm volatile("ldmatrix.sync.aligned.m8n8.x4.shared.b16 {%0,%1,%2,%3}, [%4];"
                 : "=r"(r[0]), "=r"(r[1]), "=r"(r[2]), "=r"(r[3]) : "r"(addr));
}
__device__ __forceinline__ void cp16(uint32_t dst, const void* src) {
    asm volatile("cp.async.cg.shared.global [%0], [%1], 16;" :: "r"(dst), "l"(src));
}
__device__ __forceinline__ uint32_t smem_u32(const void* p) {
    uint32_t a;
    asm("{ .reg .u64 t; cvta.to.shared.u64 t, %1; cvt.u32.u64 %0, t; }" : "=r"(a) : "l"(p));
    return a;
}
__device__ __forceinline__ uint32_t pack_h2(float lo, float hi) {
    __half2 t = __floats2half2_rn(lo, hi);
    return *reinterpret_cast<uint32_t*>(&t);
}
__device__ __forceinline__ float2 unpack_h2(uint32_t u) {
    __half2 h = *reinterpret_cast<__half2*>(&u);
    return __half22float2(h);
}

// transpose + fp16-round W1 only (feeds gemm1; stays on main stream)
__global__ void cvt_w1(const float* __restrict__ W1) {
    int i = blockIdx.x * blockDim.x + threadIdx.x;
    if (i < W1TN) {
        int half_ = i >> 17;
        int rem  = i & 131071;
        int n = rem >> 9, k = rem & 511;
        g_w1t[i] = (k < F0) ? __float2half_rn(W1[((size_t)half_ * F0 + k) * 256 + n])
                            : __float2half_rn(0.f);
    }
}
// transpose + fp16-round W2/W3 (side stream; only needed by gemm2/3)
__global__ void cvt_w23(const float* __restrict__ W2, const float* __restrict__ W3) {
    int i = blockIdx.x * blockDim.x + threadIdx.x;
    if (i < W2TN) {
        int half_ = i >> 16;
        int rem  = i & 65535;
        int n = rem >> 8, k = rem & 255;
        g_w2t[i] = __float2half_rn(W2[((size_t)half_ * HID + k) * 256 + n]);
    } else if (i < 2 * W2TN) {
        int j = i - W2TN;
        int half_ = j >> 16;
        int rem  = j & 65535;
        int n = rem >> 8, k = rem & 255;
        g_w3t[j] = __float2half_rn(W3[((size_t)half_ * HID + k) * 256 + n]);
    }
}

// ---------------- shared GEMM config -----------------------------------------
#define AS_ROWB   80
#define A_STAGEB  (64 * AS_ROWB)             // 5120 B
#define B_STAGEB  (256 * AS_ROWB)            // 20480 B
#define SMEM_F32A (2 * A_STAGEB + 4 * B_STAGEB)   // 92160 B
#define SMEM_F16A (4 * A_STAGEB + 4 * B_STAGEB)   // 102400 B

// ---------------- layer-1 GEMM: fp32 A (register-staged), fp16 out ----------
__global__ __launch_bounds__(256, 2)
void gemm_f32A(const float* __restrict__ A, int K, int lda, int KP,
               const __half* __restrict__ Wt, const float* __restrict__ bias,
               uint32_t* __restrict__ Hq, uint32_t* __restrict__ Qb)
{
    extern __shared__ char sm[];
    const uint32_t sb  = smem_u32(sm);
    const uint32_t sbB = sb + 2 * A_STAGEB;

    const int bx = blockIdx.x;
    const int bm = blockIdx.y * 64;
    const __half* Wsel = Wt + (size_t)bx * 256 * KP;

    const int tid  = threadIdx.x;
    const int wid  = tid >> 5;
    const int lane = tid & 31;
    const int wm = (wid >> 2) * 32;
    const int wn = (wid & 3) * 64;
    const int r0 = lane >> 2, c0 = lane & 3;

    const int a_roff = (lane & 7) + ((lane >> 3) & 1) * 8;
    const int a_kb   = ((lane >> 4) & 1) * 16;
    const int b_roff = (lane & 7) + ((lane >> 4) & 1) * 8;
    const int b_kb   = ((lane >> 3) & 1) * 16;

    const int a_row = tid >> 2;
    const int a_k8  = (tid & 3) * 8;
    const int KT = KP / 32;

    float acc[2][8][4];
#pragma unroll
    for (int mi = 0; mi < 2; mi++)
#pragma unroll
        for (int ni = 0; ni < 8; ni++)
#pragma unroll
            for (int c = 0; c < 4; c++) acc[mi][ni][c] = 0.f;

    auto loadB = [&](int s) {
        const int buf = s & 3;
        const int k0  = s * 32;
#pragma unroll
        for (int i = 0; i < 4; i++) {
            int c = tid + i * 256;
            int n = c >> 2, kc = (c & 3) * 8;
            uint32_t dst = sbB + buf * B_STAGEB + n * AS_ROWB + kc * 2;
            cp16(dst, Wsel + (size_t)n * KP + k0 + kc);
        }
    };
    float4 rA0, rA1;
    auto ldgA = [&](int s) {
        int gk = s * 32 + a_k8;
        int gr = bm + a_row;
        rA0 = make_float4(0.f, 0.f, 0.f, 0.f);
        rA1 = make_float4(0.f, 0.f, 0.f, 0.f);
        if (gr < NN) {
            if (gk < K)     rA0 = *(const float4*)(A + (size_t)gr * lda + gk);
            if (gk + 4 < K) rA1 = *(const float4*)(A + (size_t)gr * lda + gk + 4);
        }
    };
    auto stsA = [&](int s) {
        uint32_t dst = sb + (s & 1) * A_STAGEB + a_row * AS_ROWB + a_k8 * 2;
        uint4 v;
        v.x = pack_h2(rA0.x, rA0.y); v.y = pack_h2(rA0.z, rA0.w);
        v.z = pack_h2(rA1.x, rA1.y); v.w = pack_h2(rA1.z, rA1.w);
        asm volatile("st.shared.v4.b32 [%0], {%1,%2,%3,%4};"
                     :: "r"(dst), "r"(v.x), "r"(v.y), "r"(v.z), "r"(v.w));
    };

    loadB(0); asm volatile("cp.async.commit_group;" ::: "memory");
    loadB(1); asm volatile("cp.async.commit_group;" ::: "memory");
    loadB(2); asm volatile("cp.async.commit_group;" ::: "memory");
    ldgA(0); stsA(0);
    ldgA(1);
    asm volatile("cp.async.wait_group 2;" ::: "memory");   // B0 ready
    __syncthreads();

    for (int s = 0; s < KT; s++) {
        if (s + 1 < KT) stsA(s + 1);
        if (s + 2 < KT) ldgA(s + 2);
        if (s + 3 < KT) loadB(s + 3);
        asm volatile("cp.async.commit_group;" ::: "memory");

        const uint32_t aB = sb  + (s & 1) * A_STAGEB;
        const uint32_t bB = sbB + (s & 3) * B_STAGEB;
#pragma unroll
        for (int ks = 0; ks < 2; ks++) {
            const int kb = ks * 32;
            uint32_t af[2][4], bfr[16];
#pragma unroll
            for (int mi = 0; mi < 2; mi++)
                ldsm4(af[mi], aB + (wm + mi * 16 + a_roff) * AS_ROWB + kb + a_kb);
#pragma unroll
            for (int nip = 0; nip < 4; nip++)
                ldsm4(&bfr[nip * 4],
                      bB + (wn + nip * 16 + b_roff) * AS_ROWB + kb + b_kb);
#pragma unroll
            for (int mi = 0; mi < 2; mi++)
#pragma unroll
                for (int nip = 0; nip < 4; nip++) {
                    mma_fp16(acc[mi][nip * 2 + 0], af[mi], bfr[nip * 4 + 0], bfr[nip * 4 + 1]);
                    mma_fp16(acc[mi][nip * 2 + 1], af[mi], bfr[nip * 4 + 2], bfr[nip * 4 + 3]);
                }
        }

        if (s + 1 < KT) asm volatile("cp.async.wait_group 2;" ::: "memory");
        __syncthreads();
    }

    uint32_t* OUT = (bx == 0) ? Hq : Qb;
    float2 b2[8];
    if (bx == 0) {
#pragma unroll
        for (int ni = 0; ni < 8; ni++) {
            int col = wn + ni * 8 + c0 * 2;
            b2[ni].x = bias[col]; b2[ni].y = bias[col + 1];
        }
    }
#pragma unroll
    for (int mi = 0; mi < 2; mi++) {
#pragma unroll
        for (int ci = 0; ci < 2; ci++) {
            int row = bm + wm + mi * 16 + r0 + ci * 8;
            if (row >= NN) continue;
#pragma unroll
            for (int ni = 0; ni < 8; ni++) {
                int col = wn + ni * 8 + c0 * 2;
                float vx = acc[mi][ni][ci * 2 + 0];
                float vy = acc[mi][ni][ci * 2 + 1];
                if (bx == 0) { vx += b2[ni].x; vy += b2[ni].y; }
                OUT[(size_t)row * 128 + (col >> 1)] = pack_h2(vx, vy);
            }
        }
    }
}

// ---------------- layers 2/3 GEMM: fp16 A via pure cp.async ------------------
__global__ __launch_bounds__(256, 2)
void gemm_f16A(const __half* __restrict__ A,   // [NN][256] fp16
               const __half* __restrict__ Wt, const float* __restrict__ bias,
               uint32_t* __restrict__ Hq, uint32_t* __restrict__ Qb)
{
    extern __shared__ char sm[];
    const uint32_t sb  = smem_u32(sm);
    const uint32_t sbB = sb + 4 * A_STAGEB;
    const int KP = KP2;                      // 256

    const int bx = blockIdx.x;
    const int bm = blockIdx.y * 64;
    const __half* Wsel = Wt + (size_t)bx * 256 * KP;

    const int tid  = threadIdx.x;
    const int wid  = tid >> 5;
    const int lane = tid & 31;
    const int wm = (wid >> 2) * 32;
    const int wn = (wid & 3) * 64;
    const int r0 = lane >> 2, c0 = lane & 3;

    const int a_roff = (lane & 7) + ((lane >> 3) & 1) * 8;
    const int a_kb   = ((lane >> 4) & 1) * 16;
    const int b_roff = (lane & 7) + ((lane >> 4) & 1) * 8;
    const int b_kb   = ((lane >> 3) & 1) * 16;
    const int KT = KP / 32;                  // 8

    float acc[2][8][4];
#pragma unroll
    for (int mi = 0; mi < 2; mi++)
#pragma unroll
        for (int ni = 0; ni < 8; ni++)
#pragma unroll
            for (int c = 0; c < 4; c++) acc[mi][ni][c] = 0.f;

    auto loadStage = [&](int s) {
        const int buf = s & 3;
        const int k0  = s * 32;
        {
            int r = tid >> 2, kc = (tid & 3) * 8;
            uint32_t dst = sb + buf * A_STAGEB + r * AS_ROWB + kc * 2;
            int gr = bm + r;
            if (gr < NN) cp16(dst, A + (size_t)gr * 256 + k0 + kc);
            else asm volatile("st.shared.v4.b32 [%0], {%1,%1,%1,%1};"
                              :: "r"(dst), "r"(0u));
        }
#pragma unroll
        for (int i = 0; i < 4; i++) {
            int c = tid + i * 256;
            int n = c >> 2, kc = (c & 3) * 8;
            uint32_t dst = sbB + buf * B_STAGEB + n * AS_ROWB + kc * 2;
            cp16(dst, Wsel + (size_t)n * KP + k0 + kc);
        }
    };

    loadStage(0); asm volatile("cp.async.commit_group;" ::: "memory");
    loadStage(1); asm volatile("cp.async.commit_group;" ::: "memory");
    loadStage(2); asm volatile("cp.async.commit_group;" ::: "memory");
    asm volatile("cp.async.wait_group 2;" ::: "memory");
    __syncthreads();

    for (int s = 0; s < KT; s++) {
        if (s + 3 < KT) loadStage(s + 3);
        asm volatile("cp.async.commit_group;" ::: "memory");

        const uint32_t aB = sb  + (s & 3) * A_STAGEB;
        const uint32_t bB = sbB + (s & 3) * B_STAGEB;
#pragma unroll
        for (int ks = 0; ks < 2; ks++) {
            const int kb = ks * 32;
            uint32_t af[2][4], bfr[16];
#pragma unroll
            for (int mi = 0; mi < 2; mi++)
                ldsm4(af[mi], aB + (wm + mi * 16 + a_roff) * AS_ROWB + kb + a_kb);
#pragma unroll
            for (int nip = 0; nip < 4; nip++)
                ldsm4(&bfr[nip * 4],
                      bB + (wn + nip * 16 + b_roff) * AS_ROWB + kb + b_kb);
#pragma unroll
            for (int mi = 0; mi < 2; mi++)
#pragma unroll
                for (int nip = 0; nip < 4; nip++) {
                    mma_fp16(acc[mi][nip * 2 + 0], af[mi], bfr[nip * 4 + 0], bfr[nip * 4 + 1]);
                    mma_fp16(acc[mi][nip * 2 + 1], af[mi], bfr[nip * 4 + 2], bfr[nip * 4 + 3]);
                }
        }

        if (s + 1 < KT) asm volatile("cp.async.wait_group 2;" ::: "memory");
        __syncthreads();
    }

    uint32_t* OUT = (bx == 0) ? Hq : Qb;
    float2 b2[8];
    if (bx == 0) {
#pragma unroll
        for (int ni = 0; ni < 8; ni++) {
            int col = wn + ni * 8 + c0 * 2;
            b2[ni].x = bias[col]; b2[ni].y = bias[col + 1];
        }
    }
#pragma unroll
    for (int mi = 0; mi < 2; mi++) {
#pragma unroll
        for (int ci = 0; ci < 2; ci++) {
            int row = bm + wm + mi * 16 + r0 + ci * 8;
            if (row >= NN) continue;
#pragma unroll
            for (int ni = 0; ni < 8; ni++) {
                int col = wn + ni * 8 + c0 * 2;
                float vx = acc[mi][ni][ci * 2 + 0];
                float vy = acc[mi][ni][ci * 2 + 1];
                if (bx == 0) { vx += b2[ni].x; vy += b2[ni].y; }
                OUT[(size_t)row * 128 + (col >> 1)] = pack_h2(vx, vy);
            }
        }
    }
}

// ---------------- gather SpMM (layers 1/2): H = relu(H + sum w*Q[src]) ------
// CSR packed int2 {src, w}: one 8B load per edge.
__global__ __launch_bounds__(256)
void spmm_kernel(const uint32_t* __restrict__ Q, uint32_t* __restrict__ H) {
    int gw   = (blockIdx.x * blockDim.x + threadIdx.x) >> 5;
    int lane = threadIdx.x & 31;
    if (gw >= NN) return;
    int beg = g_row_start[gw];
    int end = beg + g_cnt[gw];

    const uint4* Q4 = (const uint4*)Q;
    float acc[8];
#pragma unroll
    for (int i = 0; i < 8; i++) acc[i] = 0.f;

#define ACCUM(u, w, o) { float2 f = unpack_h2(u); acc[o] += (w) * f.x; acc[o+1] += (w) * f.y; }

    int j = beg;
    for (; j + 4 <= end; j += 4) {
        int2 e0 = g_csr[j],     e1 = g_csr[j + 1];
        int2 e2 = g_csr[j + 2], e3 = g_csr[j + 3];
        float w0 = __int_as_float(e0.y), w1 = __int_as_float(e1.y);
        float w2 = __int_as_float(e2.y), w3 = __int_as_float(e3.y);
        uint4 a = Q4[(size_t)e0.x * 32 + lane];
        uint4 b = Q4[(size_t)e1.x * 32 + lane];
        uint4 c = Q4[(size_t)e2.x * 32 + lane];
        uint4 d = Q4[(size_t)e3.x * 32 + lane];
        ACCUM(a.x, w0, 0) ACCUM(a.y, w0, 2) ACCUM(a.z, w0, 4) ACCUM(a.w, w0, 6)
        ACCUM(b.x, w1, 0) ACCUM(b.y, w1, 2) ACCUM(b.z, w1, 4) ACCUM(b.w, w1, 6)
        ACCUM(c.x, w2, 0) ACCUM(c.y, w2, 2) ACCUM(c.z, w2, 4) ACCUM(c.w, w2, 6)
        ACCUM(d.x, w3, 0) ACCUM(d.y, w3, 2) ACCUM(d.z, w3, 4) ACCUM(d.w, w3, 6)
    }
    for (; j < end; j++) {
        int2 e0 = g_csr[j];
        float w0 = __int_as_float(e0.y);
        uint4 a = Q4[(size_t)e0.x * 32 + lane];
        ACCUM(a.x, w0, 0) ACCUM(a.y, w0, 2) ACCUM(a.z, w0, 4) ACCUM(a.w, w0, 6)
    }

    uint4* H4 = (uint4*)H;
    size_t base = (size_t)gw * 32 + lane;
    uint4 hv = H4[base];
    float2 f0 = unpack_h2(hv.x), f1 = unpack_h2(hv.y);
    float2 f2 = unpack_h2(hv.z), f3 = unpack_h2(hv.w);
    hv.x = pack_h2(fmaxf(f0.x + acc[0], 0.f), fmaxf(f0.y + acc[1], 0.f));
    hv.y = pack_h2(fmaxf(f1.x + acc[2], 0.f), fmaxf(f1.y + acc[3], 0.f));
    hv.z = pack_h2(fmaxf(f2.x + acc[4], 0.f), fmaxf(f2.y + acc[5], 0.f));
    hv.w = pack_h2(fmaxf(f3.x + acc[6], 0.f), fmaxf(f3.y + acc[7], 0.f));
    H4[base] = hv;
}

// ---------------- fused spmm3 + head ----------------------------------------
__global__ __launch_bounds__(256)
void spmm3_head(const uint32_t* __restrict__ Q, const uint32_t* __restrict__ P3,
                const float* __restrict__ Wl, const float* __restrict__ bl,
                float* __restrict__ out) {
    __shared__ float sW[768 * NC];
    int tid = threadIdx.x;
    for (int i = tid; i < 768 * NC; i += blockDim.x) sW[i] = Wl[i];
    __syncthreads();

    int gw   = (blockIdx.x * blockDim.x + tid) >> 5;
    int lane = tid & 31;
    if (gw >= NN) return;
    int beg = g_row_start[gw];
    int end = beg + g_cnt[gw];

    const uint4* Q4 = (const uint4*)Q;
    float acc[8];
#pragma unroll
    for (int i = 0; i < 8; i++) acc[i] = 0.f;

    int j = beg;
    for (; j + 4 <= end; j += 4) {
        int2 e0 = g_csr[j],     e1 = g_csr[j + 1];
        int2 e2 = g_csr[j + 2], e3 = g_csr[j + 3];
        float w0 = __int_as_float(e0.y), w1 = __int_as_float(e1.y);
        float w2 = __int_as_float(e2.y), w3 = __int_as_float(e3.y);
        uint4 a = Q4[(size_t)e0.x * 32 + lane];
        uint4 b = Q4[(size_t)e1.x * 32 + lane];
        uint4 c = Q4[(size_t)e2.x * 32 + lane];
        uint4 d = Q4[(size_t)e3.x * 32 + lane];
        ACCUM(a.x, w0, 0) ACCUM(a.y, w0, 2) ACCUM(a.z, w0, 4) ACCUM(a.w, w0, 6)
        ACCUM(b.x, w1, 0) ACCUM(b.y, w1, 2) ACCUM(b.z, w1, 4) ACCUM(b.w, w1, 6)
        ACCUM(c.x, w2, 0) ACCUM(c.y, w2, 2) ACCUM(c.z, w2, 4) ACCUM(c.w, w2, 6)
        ACCUM(d.x, w3, 0) ACCUM(d.y, w3, 2) ACCUM(d.z, w3, 4) ACCUM(d.w, w3, 6)
    }
    for (; j < end; j++) {
        int2 e0 = g_csr[j];
        float w0 = __int_as_float(e0.y);
        uint4 a = Q4[(size_t)e0.x * 32 + lane];
        ACCUM(a.x, w0, 0) ACCUM(a.y, w0, 2) ACCUM(a.z, w0, 4) ACCUM(a.w, w0, 6)
    }
#undef ACCUM

    const uint4* P34 = (const uint4*)P3;
    size_t base = (size_t)gw * 32 + lane;
    uint4 pv = P34[base];
    float h3v[8];
    {
        float2 f0 = unpack_h2(pv.x), f1 = unpack_h2(pv.y);
        float2 f2 = unpack_h2(pv.z), f3 = unpack_h2(pv.w);
        h3v[0] = fmaxf(f0.x + acc[0], 0.f); h3v[1] = fmaxf(f0.y + acc[1], 0.f);
        h3v[2] = fmaxf(f1.x + acc[2], 0.f); h3v[3] = fmaxf(f1.y + acc[3], 0.f);
        h3v[4] = fmaxf(f2.x + acc[4], 0.f); h3v[5] = fmaxf(f2.y + acc[5], 0.f);
        h3v[6] = fmaxf(f3.x + acc[6], 0.f); h3v[7] = fmaxf(f3.y + acc[7], 0.f);
    }

    uint4 h1v = ((const uint4*)g_h1)[base];
    uint4 h2v = ((const uint4*)g_h2)[base];
    float lacc[NC];
#pragma unroll
    for (int c = 0; c < NC; c++) lacc[c] = 0.f;

    int k0 = lane * 8;
    const uint32_t u1[4] = {h1v.x, h1v.y, h1v.z, h1v.w};
    const uint32_t u2[4] = {h2v.x, h2v.y, h2v.z, h2v.w};
#pragma unroll
    for (int p = 0; p < 4; p++) {
        float2 v1 = unpack_h2(u1[p]);
        float2 v2 = unpack_h2(u2[p]);
        int k = k0 + p * 2;
#pragma unroll
        for (int c = 0; c < NC; c++) {
            lacc[c] += v1.x * sW[k * NC + c]         + v1.y * sW[(k + 1) * NC + c]
                     + v2.x * sW[(256 + k) * NC + c] + v2.y * sW[(257 + k) * NC + c]
                     + h3v[p * 2]     * sW[(512 + k) * NC + c]
                     + h3v[p * 2 + 1] * sW[(513 + k) * NC + c];
        }
    }
#pragma unroll
    for (int c = 0; c < NC; c++)
        for (int off = 16; off > 0; off >>= 1)
            lacc[c] += __shfl_down_sync(0xffffffffu, lacc[c], off);

    if (lane == 0) {
        float lg[NC], mx = -1e30f;
#pragma unroll
        for (int c = 0; c < NC; c++) { lg[c] = lacc[c] + bl[c]; mx = fmaxf(mx, lg[c]); }
        float s = 0.f;
#pragma unroll
        for (int c = 0; c < NC; c++) s += expf(lg[c] - mx);
        float lse = mx + logf(s);
#pragma unroll
        for (int c = 0; c < NC; c++) out[(size_t)gw * NC + c] = lg[c] - lse;
    }
}

// ---------------------------------------------------------------------------
extern "C" void kernel_launch(void* const* d_in, const int* in_sizes, int n_in,
                              void* d_out, int out_size) {
    const float* x  = (const float*)d_in[0];
    const int*   ei = (const int*)d_in[1];
    const float* ew = (const float*)d_in[2];
    const float* W1 = (const float*)d_in[3];
    const float* b1 = (const float*)d_in[4];
    const float* W2 = (const float*)d_in[5];
    const float* b2 = (const float*)d_in[6];
    const float* W3 = (const float*)d_in[7];
    const float* b3 = (const float*)d_in[8];
    const float* Wl = (const float*)d_in[9];
    const float* bl = (const float*)d_in[10];
    float* out = (float*)d_out;

    const int* src = ei;
    const int* dst = ei + NE;

    uint32_t *h1, *h2, *p3, *q;
    __half *w1t, *w2t, *w3t;
    cudaGetSymbolAddress((void**)&h1,  g_h1);
    cudaGetSymbolAddress((void**)&h2,  g_h2);
    cudaGetSymbolAddress((void**)&p3,  g_p3);
    cudaGetSymbolAddress((void**)&q,   g_q);
    cudaGetSymbolAddress((void**)&w1t, g_w1t);
    cudaGetSymbolAddress((void**)&w2t, g_w2t);
    cudaGetSymbolAddress((void**)&w3t, g_w3t);

    cudaFuncSetAttribute(gemm_f32A, cudaFuncAttributeMaxDynamicSharedMemorySize, SMEM_F32A);
    cudaFuncSetAttribute(gemm_f16A, cudaFuncAttributeMaxDynamicSharedMemorySize, SMEM_F16A);

    // one-time side stream + fork/join events
    static cudaStream_t s2 = nullptr;
    static cudaEvent_t evFork = nullptr, evJoin = nullptr;
    if (s2 == nullptr) {
        cudaStreamCreateWithFlags(&s2, cudaStreamNonBlocking);
        cudaEventCreateWithFlags(&evFork, cudaEventDisableTiming);
        cudaEventCreateWithFlags(&evJoin, cudaEventDisableTiming);
    }

    const int T = 256;
    dim3 gemm_grid(2, (NN + 63) / 64);     // 2 x 1395
    const int node_warps = (NN + 7) / 8;

    // ---- fork: CSR build + w2/w3 conversion run concurrently with gemm1 ----
    cudaEventRecord(evFork, 0);
    cudaStreamWaitEvent(s2, evFork, 0);

    zero_cnt<<<NBLK, SCAN_T, 0, s2>>>();
    count_kernel<<<(NE + T - 1) / T, T, 0, s2>>>(dst);

    cvt_w1<<<(W1TN + T - 1) / T, T>>>(W1);
    gemm_f32A<<<gemm_grid, T, SMEM_F32A>>>(x, F0, F0, KP1, w1t, b1, h1, q); // profiled slot
    scanA<<<NBLK, SCAN_T, 0, s2>>>();
    scanB<<<1, 512, 0, s2>>>();
    scanC<<<NBLK, SCAN_T, 0, s2>>>();
    place_kernel<<<(NE + T - 1) / T, T, 0, s2>>>(src, dst, ew);
    cvt_w23<<<(2 * W2TN + T - 1) / T, T, 0, s2>>>(W2, W3);
    cudaEventRecord(evJoin, s2);

    // ---- join ----
    cudaStreamWaitEvent(0, evJoin, 0);

    spmm_kernel<<<node_warps, T>>>(q, h1);

    gemm_f16A<<<gemm_grid, T, SMEM_F16A>>>((const __half*)h1, w2t, b2, h2, q);
    spmm_kernel<<<node_warps, T>>>(q, h2);

    gemm_f16A<<<gemm_grid, T, SMEM_F16A>>>((const __half*)h2, w3t, b3, p3, q);
    spmm3_head<<<node_warps, T>>>(q, p3, Wl, bl, out);
}